// round 6
// baseline (speedup 1.0000x reference)
#include <cuda_runtime.h>
#include <cuda_bf16.h>
#include <cstdint>
#include <cstring>

// Problem constants
#define K_STATES 64
#define D_DIM    512
#define BATCH    512
#define T_FULL   128
#define T_STEPS  126            // real word positions 1..126
#define P_TOTAL  (BATCH * T_STEPS)   // 64512
#define BOS_TAG  63
#define EOS_TAG  62

// Scratch: emission logits L[p][k] = ThetaB[k] . E[words[p]]
__device__ float g_L[(size_t)P_TOTAL * K_STATES];   // 16.5 MB

static __device__ __forceinline__ uint32_t pack_bf16x2(float x, float y) {
    __nv_bfloat162 p = __floats2bfloat162_rn(x, y);
    uint32_t u;
    memcpy(&u, &p, 4);
    return u;
}

// ---------------------------------------------------------------------------
// Kernel 1: gathered GEMM  L[p][k] = sum_d E[word_p][d] * ThetaB[k][d]
// bf16 mma.sync m16n8k16, fp32 accumulate. CTA tile: 64 positions x 64 states.
// E rows (DRAM-gather) are register-prefetched one chunk ahead.
// ---------------------------------------------------------------------------
#define PTILE     64
#define CHUNK     64
#define S_STRIDE  72   // bf16 elems per shared row (64 + 8 pad)

__global__ __launch_bounds__(128) void emit_gemm_kernel(
    const float* __restrict__ ThetaB,
    const float* __restrict__ E,
    const int*   __restrict__ words)
{
    __shared__ __nv_bfloat16 Es [PTILE    * S_STRIDE];
    __shared__ __nv_bfloat16 Ths[K_STATES * S_STRIDE];
    __shared__ int sWord[PTILE];

    const int tid    = threadIdx.x;
    const int p_base = blockIdx.x * PTILE;

    if (tid < PTILE) {
        int p = p_base + tid;
        int b = p / T_STEPS;
        int t = p - b * T_STEPS;
        sWord[tid] = words[b * T_FULL + t + 1];
    }
    __syncthreads();

    const int lane = tid & 31;
    const int warp = tid >> 5;
    const int g    = lane >> 2;
    const int tig  = lane & 3;
    const int wrow = warp * 16;

    float c[8][4];
    #pragma unroll
    for (int nt = 0; nt < 8; nt++)
        #pragma unroll
        for (int i = 0; i < 4; i++) c[nt][i] = 0.f;

    float4 ev[8];
    #pragma unroll
    for (int i = 0; i < 8; i++) {
        int flat = tid + 128 * i;
        int row  = flat >> 4;
        int seg  = flat & 15;
        ev[i] = *(const float4*)&E[(size_t)sWord[row] * D_DIM + seg * 4];
    }

    for (int ch = 0; ch < D_DIM / CHUNK; ch++) {
        const int doff = ch * CHUNK;

        #pragma unroll
        for (int i = 0; i < 8; i++) {
            int flat = tid + 128 * i;
            int row  = flat >> 4;
            int seg  = flat & 15;
            uint32_t* dst = (uint32_t*)&Es[row * S_STRIDE + seg * 4];
            dst[0] = pack_bf16x2(ev[i].x, ev[i].y);
            dst[1] = pack_bf16x2(ev[i].z, ev[i].w);
        }
        #pragma unroll
        for (int i = 0; i < 8; i++) {
            int flat = tid + 128 * i;
            int row  = flat >> 4;
            int seg  = flat & 15;
            float4 v = *(const float4*)&ThetaB[row * D_DIM + doff + seg * 4];
            uint32_t* dst = (uint32_t*)&Ths[row * S_STRIDE + seg * 4];
            dst[0] = pack_bf16x2(v.x, v.y);
            dst[1] = pack_bf16x2(v.z, v.w);
        }
        __syncthreads();

        if (ch + 1 < D_DIM / CHUNK) {
            #pragma unroll
            for (int i = 0; i < 8; i++) {
                int flat = tid + 128 * i;
                int row  = flat >> 4;
                int seg  = flat & 15;
                ev[i] = *(const float4*)&E[(size_t)sWord[row] * D_DIM + doff + CHUNK + seg * 4];
            }
        }

        #pragma unroll
        for (int ks = 0; ks < 4; ks++) {
            const int kof = ks * 16;
            uint32_t a0 = *(const uint32_t*)&Es[(wrow + g    ) * S_STRIDE + kof + 2 * tig    ];
            uint32_t a1 = *(const uint32_t*)&Es[(wrow + g + 8) * S_STRIDE + kof + 2 * tig    ];
            uint32_t a2 = *(const uint32_t*)&Es[(wrow + g    ) * S_STRIDE + kof + 2 * tig + 8];
            uint32_t a3 = *(const uint32_t*)&Es[(wrow + g + 8) * S_STRIDE + kof + 2 * tig + 8];
            #pragma unroll
            for (int nt = 0; nt < 8; nt++) {
                uint32_t b0 = *(const uint32_t*)&Ths[(nt * 8 + g) * S_STRIDE + kof + 2 * tig    ];
                uint32_t b1 = *(const uint32_t*)&Ths[(nt * 8 + g) * S_STRIDE + kof + 2 * tig + 8];
                asm volatile(
                    "mma.sync.aligned.m16n8k16.row.col.f32.bf16.bf16.f32 "
                    "{%0,%1,%2,%3}, {%4,%5,%6,%7}, {%8,%9}, {%0,%1,%2,%3};"
                    : "+f"(c[nt][0]), "+f"(c[nt][1]), "+f"(c[nt][2]), "+f"(c[nt][3])
                    : "r"(a0), "r"(a1), "r"(a2), "r"(a3), "r"(b0), "r"(b1));
            }
        }
        __syncthreads();
    }

    #pragma unroll
    for (int nt = 0; nt < 8; nt++) {
        int col  = nt * 8 + 2 * tig;
        size_t r0 = (size_t)(p_base + wrow + g) * K_STATES + col;
        size_t r1 = (size_t)(p_base + wrow + g + 8) * K_STATES + col;
        *(float2*)&g_L[r0] = make_float2(c[nt][0], c[nt][1]);
        *(float2*)&g_L[r1] = make_float2(c[nt][2], c[nt][3]);
    }
}

// ---------------------------------------------------------------------------
// Kernel 2: forward recursion, one CTA (128 threads = 4 warps) per sequence.
// Thread pair (2c, 2c+1) owns column c: thread h in {0,1} holds
// A[32h..32h+31][c] in 32 registers and computes a half dot product;
// the halves combine with one shfl_xor(1) (same warp).
// Rescale (max + log) only every 8 steps.
// ---------------------------------------------------------------------------
__global__ __launch_bounds__(128) void forward_kernel(
    const float* __restrict__ WA,
    const int*   __restrict__ tags,
    float*       __restrict__ out)
{
    __shared__ __align__(16) float abuf[2][K_STATES];
    __shared__ float red[4];

    const int tid  = threadIdx.x;
    const int c    = tid >> 1;          // column / state 0..63
    const int h    = tid & 1;           // half 0/1
    const int lane = tid & 31;
    const int warp = tid >> 5;
    const int seq  = blockIdx.x;

    // Half of A column c: Ah[j2] = exp(WA[(32h+j2)][c]); column BOS forbidden.
    float Ah[32];
    #pragma unroll
    for (int j2 = 0; j2 < 32; j2++) {
        float v = __expf(WA[(32 * h + j2) * K_STATES + c]);
        Ah[j2] = (c == BOS_TAG) ? 0.f : v;
    }

    const float* Lseq = &g_L[(size_t)seq * T_STEPS * K_STATES];

    if (h == 0) abuf[0][c] = (c == BOS_TAG) ? 1.f : 0.f;
    __syncthreads();

    // Rolling emission prefetch (2 steps ahead)
    float Lcur  = Lseq[c];
    float Lnext = Lseq[K_STATES + c];

    float logsum = 0.f;
    float s = 0.f;

    for (int t = 0; t < T_STEPS; t++) {
        const float4* ab = (const float4*)abuf[t & 1] + 8 * h;
        float a0 = 0.f, a1 = 0.f, a2 = 0.f, a3 = 0.f;
        #pragma unroll
        for (int q = 0; q < 8; q++) {
            float4 av = ab[q];
            a0 = fmaf(av.x, Ah[4 * q    ], a0);
            a1 = fmaf(av.y, Ah[4 * q + 1], a1);
            a2 = fmaf(av.z, Ah[4 * q + 2], a2);
            a3 = fmaf(av.w, Ah[4 * q + 3], a3);
        }
        s = (a0 + a1) + (a2 + a3);
        s += __shfl_xor_sync(0xffffffffu, s, 1);   // combine halves (same warp)

        float e = __expf(Lcur);
        if (c >= EOS_TAG) e = 0.f;      // EOS/BOS emissions clamped ~0
        s *= e;

        Lcur = Lnext;
        if (t + 2 < T_STEPS) Lnext = Lseq[(size_t)(t + 2) * K_STATES + c];

        if ((t & 7) == 7) {
            // periodic rescale: m = max over all columns
            float m = s;
            #pragma unroll
            for (int off = 16; off > 1; off >>= 1)
                m = fmaxf(m, __shfl_xor_sync(0xffffffffu, m, off));
            if (lane == 0) red[warp] = m;
            __syncthreads();
            m = fmaxf(fmaxf(red[0], red[1]), fmaxf(red[2], red[3]));
            logsum += __logf(m);
            s = __fdividef(s, m);
        }

        if (h == 0) abuf[(t + 1) & 1][c] = s;
        __syncthreads();
    }

    // val = alpha . A[:, EOS]; only h==0 contributes (both halves hold same s)
    float pv = (h == 0) ? s * __expf(WA[c * K_STATES + EOS_TAG]) : 0.f;
    #pragma unroll
    for (int off = 16; off; off >>= 1)
        pv += __shfl_xor_sync(0xffffffffu, pv, off);
    if (lane == 0) red[warp] = pv;
    __syncthreads();
    float unsup = __logf((red[0] + red[1]) + (red[2] + red[3])) + logsum;
    __syncthreads();

    // Tagged score: closed form (one-hot support makes alpha rank-1 each step)
    const int* tg = &tags[seq * T_FULL];
    float tsum = 0.f;
    for (int p = 1 + tid; p <= T_STEPS; p += 128) {
        int cur  = tg[p];
        int prev = (p == 1) ? BOS_TAG : tg[p - 1];
        tsum += WA[prev * K_STATES + cur] + Lseq[(size_t)(p - 1) * K_STATES + cur];
    }
    #pragma unroll
    for (int off = 16; off; off >>= 1)
        tsum += __shfl_xor_sync(0xffffffffu, tsum, off);
    if (lane == 0) red[warp] = tsum;
    __syncthreads();

    if (tid == 0) {
        float tagged = (red[0] + red[1]) + (red[2] + red[3])
                     + WA[tg[T_STEPS] * K_STATES + EOS_TAG];
        out[seq] = tagged - unsup;
    }
}

// ---------------------------------------------------------------------------
extern "C" void kernel_launch(void* const* d_in, const int* in_sizes, int n_in,
                              void* d_out, int out_size)
{
    const float* WA     = (const float*)d_in[0];
    const float* ThetaB = (const float*)d_in[1];
    const float* E      = (const float*)d_in[2];
    const int*   words  = (const int*)  d_in[3];
    const int*   tags   = (const int*)  d_in[4];
    float*       out    = (float*)d_out;

    emit_gemm_kernel<<<P_TOTAL / PTILE, 128>>>(ThetaB, E, words);
    forward_kernel<<<BATCH, 128>>>(WA, tags, out);
}